// round 8
// baseline (speedup 1.0000x reference)
#include <cuda_runtime.h>
#include <cstdint>

// ---------------------------------------------------------------------------
// PointNet++ (3 SA stages), B=64, N=4096, fp32.
// Round 8: stage1/2 MLPs on tensor cores via mma.sync.m16n8k8.tf32 with
// 3xTF32 split precision (fp32-class accuracy). Stage0 stays SIMT/FFMA2.
// ---------------------------------------------------------------------------

static constexpr int B   = 64;
static constexpr int N0  = 4096;
static constexpr int S0  = 128, NSAMP0 = 32;
static constexpr int S1  = 64;
static constexpr int S2  = 32;

// ------------------------- device scratch (no allocs) ----------------------
__device__ float g_nx1[B * S0 * 3];
__device__ float g_nx2[B * S1 * 3];
__device__ float g_nx3[B * S2 * 3];
__device__ int   g_idxbuf[B * S0 * NSAMP0];
__device__ float g_f1[B * S0 * 64];
__device__ float g_f2[B * S1 * 128];

// stage0 (SIMT): k-major folded weights, CIN folded 9->6
__device__ __align__(16) float g_w0T[6 * 32];     __device__ __align__(16) float g_b0[32];
__device__ __align__(16) float g_w1T[32 * 64];    __device__ __align__(16) float g_b1[64];
// stage1/2 (mma): row-major o x kpad folded weights (zero padded)
__device__ __align__(16) float g_w2M[128 * 72];   __device__ __align__(16) float g_b2[128];
__device__ __align__(16) float g_w3M[128 * 128];  __device__ __align__(16) float g_b3[128];
__device__ __align__(16) float g_w4M[256 * 136];  __device__ __align__(16) float g_b4[256];
__device__ __align__(16) float g_w5M[256 * 256];  __device__ __align__(16) float g_b5[256];

// ------------------------- f32x2 helpers (stage0 SIMT) ---------------------
typedef unsigned long long u64;

__device__ __forceinline__ u64 pack2(float x) {
    u64 r;
    asm("mov.b64 %0, {%1, %2};" : "=l"(r) : "f"(x), "f"(x));
    return r;
}
__device__ __forceinline__ void unpack2(u64 v, float& lo, float& hi) {
    asm("mov.b64 {%0, %1}, %2;" : "=f"(lo), "=f"(hi) : "l"(v));
}
__device__ __forceinline__ u64 ffma2(u64 a, u64 b, u64 c) {
    u64 d;
    asm("fma.rn.f32x2 %0, %1, %2, %3;" : "=l"(d) : "l"(a), "l"(b), "l"(c));
    return d;
}

// ------------------------- tf32 helpers ------------------------------------
__device__ __forceinline__ void split_tf32(float x, uint32_t& hi, uint32_t& lo) {
    asm("cvt.rna.tf32.f32 %0, %1;" : "=r"(hi) : "f"(x));
    float hif = __uint_as_float(hi);
    float lof = __fsub_rn(x, hif);
    asm("cvt.rna.tf32.f32 %0, %1;" : "=r"(lo) : "f"(lof));
}
__device__ __forceinline__ void mma_tf32(float* c, const uint32_t* a, const uint32_t* b) {
    asm("mma.sync.aligned.m16n8k8.row.col.f32.tf32.tf32.f32 "
        "{%0,%1,%2,%3}, {%4,%5,%6,%7}, {%8,%9}, {%0,%1,%2,%3};"
        : "+f"(c[0]), "+f"(c[1]), "+f"(c[2]), "+f"(c[3])
        : "r"(a[0]), "r"(a[1]), "r"(a[2]), "r"(a[3]), "r"(b[0]), "r"(b[1]));
}

// ------------------------- merged BN fold ----------------------------------
struct FoldArgs {
    const float* w[6]; const float* g[6]; const float* be[6];
    const float* rm[6]; const float* rv[6];
    float* wT[6]; float* bias[6];
    int cin[6]; int cinP[6]; int cout[6];
};

__global__ void fold_all_kernel(FoldArgs a)
{
    int l = blockIdx.y;
    int cin = a.cin[l], cinP = a.cinP[l], cout = a.cout[l];
    const float* w = a.w[l]; const float* g = a.g[l]; const float* be = a.be[l];
    const float* rm = a.rm[l]; const float* rv = a.rv[l];
    float* wT = a.wT[l]; float* bias = a.bias[l];
    int i = blockIdx.x * blockDim.x + threadIdx.x;
    if (i < cout) {
        float s = g[i] * rsqrtf(rv[i] + 1e-5f);
        bias[i] = be[i] - s * rm[i];
    }
    if (l == 0) {
        // k-major, fold 9 -> 6 rows (dup abs-xyz): rows 3..5 = W[:,3+t]+W[:,6+t]
        int tot = cout * 6;
        for (int e = i; e < tot; e += gridDim.x * blockDim.x) {
            int o = e / 6, k = e - o * 6;
            float s = g[o] * rsqrtf(rv[o] + 1e-5f);
            float val = (k < 3) ? w[o * 9 + k] : (w[o * 9 + k] + w[o * 9 + k + 3]);
            wT[k * cout + o] = val * s;
        }
    } else if (l == 1) {
        // k-major
        int tot = cout * cin;
        for (int e = i; e < tot; e += gridDim.x * blockDim.x) {
            int o = e / cin, k = e - o * cin;
            float s = g[o] * rsqrtf(rv[o] + 1e-5f);
            wT[k * cout + o] = w[e] * s;
        }
    } else {
        // row-major o x kpad, zero pad
        int tot = cout * cinP;
        for (int e = i; e < tot; e += gridDim.x * blockDim.x) {
            int o = e / cinP, k = e - o * cinP;
            float s = g[o] * rsqrtf(rv[o] + 1e-5f);
            wT[e] = (k < cin) ? w[o * cin + k] * s : 0.0f;
        }
    }
}

// ------------------------- farthest point sampling -------------------------
template<int N, int NPOINT, int T>
__global__ void __launch_bounds__(T) fps_kernel(const float* __restrict__ xyz,
                                                float* __restrict__ newxyz)
{
    constexpr int PPT = N / T;
    int b = blockIdx.x;
    int tid = threadIdx.x;
    const float* x = xyz + (size_t)b * N * 3;

    float px[PPT], py[PPT], pz[PPT], dist[PPT];
#pragma unroll
    for (int i = 0; i < PPT; i++) {
        int p = tid + i * T;
        px[i] = x[p * 3 + 0];
        py[i] = x[p * 3 + 1];
        pz[i] = x[p * 3 + 2];
        dist[i] = 1e10f;
    }

    __shared__ float cur[3];
    __shared__ float wv[T / 32];
    __shared__ int   wi[T / 32];

    if (tid == 0) {
        cur[0] = x[0]; cur[1] = x[1]; cur[2] = x[2];
        float* o = newxyz + (size_t)b * NPOINT * 3;
        o[0] = x[0]; o[1] = x[1]; o[2] = x[2];
    }
    __syncthreads();

    for (int j = 1; j < NPOINT; j++) {
        float cx = cur[0], cy = cur[1], cz = cur[2];
        float bv = -1.0f;
        int   bi = 0x7fffffff;
#pragma unroll
        for (int i = 0; i < PPT; i++) {
            float dx = px[i] - cx, dy = py[i] - cy, dz = pz[i] - cz;
            float d = __fadd_rn(__fadd_rn(__fmul_rn(dx, dx), __fmul_rn(dy, dy)),
                                __fmul_rn(dz, dz));
            float nd = fminf(dist[i], d);
            dist[i] = nd;
            int gidx = tid + i * T;
            if (nd > bv || (nd == bv && gidx < bi)) { bv = nd; bi = gidx; }
        }
#pragma unroll
        for (int off = 16; off > 0; off >>= 1) {
            float ov = __shfl_down_sync(0xffffffffu, bv, off);
            int   oi = __shfl_down_sync(0xffffffffu, bi, off);
            if (ov > bv || (ov == bv && oi < bi)) { bv = ov; bi = oi; }
        }
        if ((tid & 31) == 0) { wv[tid >> 5] = bv; wi[tid >> 5] = bi; }
        __syncthreads();
        if (tid < 32) {
            constexpr int NW = T / 32;
            bv = (tid < NW) ? wv[tid] : -2.0f;
            bi = (tid < NW) ? wi[tid] : 0x7fffffff;
#pragma unroll
            for (int off = 16; off > 0; off >>= 1) {
                float ov = __shfl_down_sync(0xffffffffu, bv, off);
                int   oi = __shfl_down_sync(0xffffffffu, bi, off);
                if (ov > bv || (ov == bv && oi < bi)) { bv = ov; bi = oi; }
            }
            if (tid == 0) {
                const float* p = x + (size_t)bi * 3;
                float nx = p[0], ny = p[1], nz = p[2];
                cur[0] = nx; cur[1] = ny; cur[2] = nz;
                float* o = newxyz + ((size_t)b * NPOINT + j) * 3;
                o[0] = nx; o[1] = ny; o[2] = nz;
            }
        }
        __syncthreads();
    }
}

// ------------------------- ball query --------------------------------------
template<int NS>
__global__ void ballquery_kernel(const float* __restrict__ newxyz,
                                 const float* __restrict__ xyz,
                                 int* __restrict__ idxout,
                                 int N, int S, float rr)
{
    __shared__ int rows[4][NS];
    int lane = threadIdx.x & 31;
    int wip  = threadIdx.x >> 5;
    int q = blockIdx.x * 4 + wip;
    int b = q / S;
    const float* nq = newxyz + (size_t)q * 3;
    float qx = nq[0], qy = nq[1], qz = nq[2];
    const float* x = xyz + (size_t)b * N * 3;
    int* row = rows[wip];
    int cnt = 0;

    for (int base = 0; base < N; base += 32) {
        if (cnt >= NS) break;
        int p = base + lane;
        float dx = x[p * 3 + 0] - qx;
        float dy = x[p * 3 + 1] - qy;
        float dz = x[p * 3 + 2] - qz;
        float d = __fadd_rn(__fadd_rn(__fmul_rn(dx, dx), __fmul_rn(dy, dy)),
                            __fmul_rn(dz, dz));
        bool hit = d < rr;
        unsigned m = __ballot_sync(0xffffffffu, hit);
        if (hit) {
            int pos = cnt + __popc(m & ((1u << lane) - 1u));
            if (pos < NS) row[pos] = p;
        }
        cnt += __popc(m);
    }
    __syncwarp();
    int first = (cnt > 0) ? row[0] : 0;
    for (int t = cnt + lane; t < NS; t += 32) row[t] = first;
    __syncwarp();
    for (int t = lane; t < NS; t += 32) idxout[(size_t)q * NS + t] = row[t];
}

// ------------------------- stage0 SIMT MLP (unchanged from R6) --------------
template<int CIN, int C0, int C1, int NS, int G, int T, int NO0, int NO1>
__global__ void __launch_bounds__(T) sa_mlp0_kernel(
    const float* __restrict__ xyz,
    const float* __restrict__ newxyz, const int* __restrict__ idx,
    const float* __restrict__ w0T, const float* __restrict__ b0,
    const float* __restrict__ w1T, const float* __restrict__ b1,
    float* __restrict__ out, int N, int S)
{
    constexpr int SB = NS * G;
    constexpr int LD = SB + 4;
    constexpr int CQ0 = C0 / 4, NGRP0 = SB / NO0;
    constexpr int CQ1 = C1 / 4, NGRP1 = SB / NO1;
    static_assert(CQ0 * NGRP0 == T, "layer0 mapping");
    static_assert(CQ1 * NGRP1 == T, "layer1 mapping");
    constexpr int OPG = NS / NO1;

    extern __shared__ __align__(16) float smem[];
    float* xs   = smem;
    float* mid  = xs + CIN * LD;
    float* pmax = mid + C0 * LD;

    int gs0 = blockIdx.x * G;
    int b = gs0 / S;
    int tid = threadIdx.x;

    int* sidx = (int*)pmax;
    for (int e = tid; e < SB; e += T)
        sidx[e] = idx[(size_t)(gs0 + e / NS) * NS + (e % NS)];
    __syncthreads();

    for (int e = tid; e < SB; e += T) {
        int g = e / NS;
        int id = sidx[e];
        const float* p = xyz + ((size_t)b * N + id) * 3;
        const float* c = newxyz + (size_t)(gs0 + g) * 3;
        float ax = p[0], ay = p[1], az = p[2];
        xs[0 * LD + e] = ax - c[0];
        xs[1 * LD + e] = ay - c[1];
        xs[2 * LD + e] = az - c[2];
        xs[3 * LD + e] = ax; xs[4 * LD + e] = ay; xs[5 * LD + e] = az;
    }
    __syncthreads();

    {
        int cq = tid % CQ0;
        int n8 = tid / CQ0;
        u64 acc[4][NO0 / 2];
        {
            float4 bv = *reinterpret_cast<const float4*>(b0 + 4 * cq);
            float bk[4] = {bv.x, bv.y, bv.z, bv.w};
#pragma unroll
            for (int i = 0; i < 4; i++) {
                u64 p = pack2(bk[i]);
#pragma unroll
                for (int j = 0; j < NO0 / 2; j++) acc[i][j] = p;
            }
        }
        const float* xrow = xs + n8 * NO0;
        const float* wptr = w0T + 4 * cq;
#pragma unroll 4
        for (int k = 0; k < CIN; k++) {
            float4 w = *reinterpret_cast<const float4*>(wptr + k * C0);
            ulonglong2 v[NO0 / 4];
            const ulonglong2* xr = reinterpret_cast<const ulonglong2*>(xrow + k * LD);
#pragma unroll
            for (int j = 0; j < NO0 / 4; j++) v[j] = xr[j];
            float wk[4] = {w.x, w.y, w.z, w.w};
#pragma unroll
            for (int i = 0; i < 4; i++) {
                u64 w2 = pack2(wk[i]);
#pragma unroll
                for (int j = 0; j < NO0 / 4; j++) {
                    acc[i][2 * j + 0] = ffma2(w2, v[j].x, acc[i][2 * j + 0]);
                    acc[i][2 * j + 1] = ffma2(w2, v[j].y, acc[i][2 * j + 1]);
                }
            }
        }
#pragma unroll
        for (int i = 0; i < 4; i++) {
            float* mrow = mid + (4 * cq + i) * LD + n8 * NO0;
#pragma unroll
            for (int j = 0; j < NO0 / 2; j++) {
                float lo, hi;
                unpack2(acc[i][j], lo, hi);
                float2 r;
                r.x = fmaxf(lo, 0.0f);
                r.y = fmaxf(hi, 0.0f);
                *reinterpret_cast<float2*>(mrow + 2 * j) = r;
            }
        }
    }
    __syncthreads();

    {
        int cq = tid % CQ1;
        int n8 = tid / CQ1;
        u64 acc[4][NO1 / 2];
        {
            float4 bv = *reinterpret_cast<const float4*>(b1 + 4 * cq);
            float bk[4] = {bv.x, bv.y, bv.z, bv.w};
#pragma unroll
            for (int i = 0; i < 4; i++) {
                u64 p = pack2(bk[i]);
#pragma unroll
                for (int j = 0; j < NO1 / 2; j++) acc[i][j] = p;
            }
        }
        const float* mrowb = mid + n8 * NO1;
        const float* wptr = w1T + 4 * cq;
#pragma unroll 4
        for (int k = 0; k < C0; k++) {
            float4 w = *reinterpret_cast<const float4*>(wptr + k * C1);
            ulonglong2 v[NO1 / 4];
            const ulonglong2* mr = reinterpret_cast<const ulonglong2*>(mrowb + k * LD);
#pragma unroll
            for (int j = 0; j < NO1 / 4; j++) v[j] = mr[j];
            float wk[4] = {w.x, w.y, w.z, w.w};
#pragma unroll
            for (int i = 0; i < 4; i++) {
                u64 w2 = pack2(wk[i]);
#pragma unroll
                for (int j = 0; j < NO1 / 4; j++) {
                    acc[i][2 * j + 0] = ffma2(w2, v[j].x, acc[i][2 * j + 0]);
                    acc[i][2 * j + 1] = ffma2(w2, v[j].y, acc[i][2 * j + 1]);
                }
            }
        }
#pragma unroll
        for (int i = 0; i < 4; i++) {
            float m = -3.4e38f;
#pragma unroll
            for (int j = 0; j < NO1 / 2; j++) {
                float lo, hi;
                unpack2(acc[i][j], lo, hi);
                m = fmaxf(m, fmaxf(lo, hi));
            }
            pmax[n8 * C1 + 4 * cq + i] = m;
        }
    }
    __syncthreads();

    for (int e = tid; e < G * C1; e += T) {
        int g = e / C1, ch = e - g * C1;
        float m = pmax[(g * OPG) * C1 + ch];
#pragma unroll
        for (int j = 1; j < OPG; j++)
            m = fmaxf(m, pmax[(g * OPG + j) * C1 + ch]);
        m = fmaxf(m, 0.0f);
        int gs = gs0 + g;
        int s = gs - b * S;
        out[(size_t)gs * C1 + ch] = m;                      // (B, S, C)
    }
}

// ------------------------- stage1/2 mma MLP ---------------------------------
// One block (128 thr, 4 warps) per group. 3xTF32: acc += ahi*bhi + ahi*blo
// + alo*bhi -> fp32-class accuracy. A = weights (row-major o x kpad, global),
// B = grouped input in smem (k x NS, pitch LDX chosen bank-conflict-free).
template<int C0, int C1, int K0, int K0P, int NS, int LDX, bool FINAL>
__global__ void __launch_bounds__(128) sa_mma_kernel(
    const float* __restrict__ xyz, const float* __restrict__ feats,
    const float* __restrict__ newxyz, const int* __restrict__ idx,
    const float* __restrict__ w0M, const float* __restrict__ b0,
    const float* __restrict__ w1M, const float* __restrict__ b1,
    float* __restrict__ out, int N, int S)
{
    constexpr int MT0 = C0 / 64;   // m16 tiles per warp (layer0)
    constexpr int MT1 = C1 / 64;
    constexpr int NT  = NS / 8;    // n8 tiles
    constexpr int K0S = K0P / 8;
    constexpr int K1S = C0 / 8;
    constexpr int CF  = K0 - 3;    // feature channels (power of 2)

    extern __shared__ __align__(16) float smem[];
    float* xs  = smem;             // K0P * LDX
    float* mid = xs + K0P * LDX;   // C0 * LDX

    int gs = blockIdx.x;
    int b = gs / S, s = gs - b * S;
    int tid = threadIdx.x;
    int lane = tid & 31, warp = tid >> 5;
    int gid = lane >> 2, tl = lane & 3;

    const int* gi = idx + (size_t)gs * NS;
    float cx = newxyz[gs * 3 + 0], cy = newxyz[gs * 3 + 1], cz = newxyz[gs * 3 + 2];

    // ---- gather ----
    for (int n = tid; n < NS; n += 128) {
        int id = gi[n];
        const float* p = xyz + ((size_t)b * N + id) * 3;
        xs[0 * LDX + n] = p[0] - cx;
        xs[1 * LDX + n] = p[1] - cy;
        xs[2 * LDX + n] = p[2] - cz;
    }
    for (int e = tid; e < CF * NS; e += 128) {
        int n = e / CF, c = e - n * CF;
        xs[(3 + c) * LDX + n] = feats[((size_t)b * N + gi[n]) * CF + c];
    }
    for (int e = tid; e < (K0P - K0) * NS; e += 128) {
        int r = e / NS, n = e - r * NS;
        xs[(K0 + r) * LDX + n] = 0.0f;
    }
    __syncthreads();

    // ---- layer 0: mid = relu(W0 @ xs + b0) ----
    {
        float acc[MT0][NT][4];
#pragma unroll
        for (int mt = 0; mt < MT0; mt++) {
            int r0 = warp * MT0 * 16 + mt * 16 + gid;
            float bb0 = b0[r0], bb1 = b0[r0 + 8];
#pragma unroll
            for (int n = 0; n < NT; n++) {
                acc[mt][n][0] = bb0; acc[mt][n][1] = bb0;
                acc[mt][n][2] = bb1; acc[mt][n][3] = bb1;
            }
        }
        for (int ks = 0; ks < K0S; ks++) {
            uint32_t ahi[MT0][4], alo[MT0][4];
#pragma unroll
            for (int mt = 0; mt < MT0; mt++) {
                int r0 = warp * MT0 * 16 + mt * 16 + gid;
                const float* wp = w0M + (size_t)r0 * K0P + ks * 8 + tl;
                split_tf32(wp[0],           ahi[mt][0], alo[mt][0]);
                split_tf32(wp[8 * K0P],     ahi[mt][1], alo[mt][1]);
                split_tf32(wp[4],           ahi[mt][2], alo[mt][2]);
                split_tf32(wp[8 * K0P + 4], ahi[mt][3], alo[mt][3]);
            }
            uint32_t bhi[NT][2], blo[NT][2];
#pragma unroll
            for (int n = 0; n < NT; n++) {
                const float* xp = xs + (ks * 8 + tl) * LDX + n * 8 + gid;
                split_tf32(xp[0],       bhi[n][0], blo[n][0]);
                split_tf32(xp[4 * LDX], bhi[n][1], blo[n][1]);
            }
#pragma unroll
            for (int mt = 0; mt < MT0; mt++)
#pragma unroll
                for (int n = 0; n < NT; n++) {
                    mma_tf32(acc[mt][n], ahi[mt], blo[n]);
                    mma_tf32(acc[mt][n], alo[mt], bhi[n]);
                    mma_tf32(acc[mt][n], ahi[mt], bhi[n]);
                }
        }
#pragma unroll
        for (int mt = 0; mt < MT0; mt++) {
            int r0 = warp * MT0 * 16 + mt * 16 + gid;
#pragma unroll
            for (int n = 0; n < NT; n++) {
                float2 v0, v1;
                v0.x = fmaxf(acc[mt][n][0], 0.0f);
                v0.y = fmaxf(acc[mt][n][1], 0.0f);
                v1.x = fmaxf(acc[mt][n][2], 0.0f);
                v1.y = fmaxf(acc[mt][n][3], 0.0f);
                *reinterpret_cast<float2*>(mid + (size_t)r0 * LDX + n * 8 + 2 * tl) = v0;
                *reinterpret_cast<float2*>(mid + (size_t)(r0 + 8) * LDX + n * 8 + 2 * tl) = v1;
            }
        }
    }
    __syncthreads();

    // ---- layer 1 + maxpool ----
    {
        float acc[MT1][NT][4];
#pragma unroll
        for (int mt = 0; mt < MT1; mt++) {
            int r0 = warp * MT1 * 16 + mt * 16 + gid;
            float bb0 = b1[r0], bb1 = b1[r0 + 8];
#pragma unroll
            for (int n = 0; n < NT; n++) {
                acc[mt][n][0] = bb0; acc[mt][n][1] = bb0;
                acc[mt][n][2] = bb1; acc[mt][n][3] = bb1;
            }
        }
        for (int ks = 0; ks < K1S; ks++) {
            uint32_t ahi[MT1][4], alo[MT1][4];
#pragma unroll
            for (int mt = 0; mt < MT1; mt++) {
                int r0 = warp * MT1 * 16 + mt * 16 + gid;
                const float* wp = w1M + (size_t)r0 * C0 + ks * 8 + tl;
                split_tf32(wp[0],          ahi[mt][0], alo[mt][0]);
                split_tf32(wp[8 * C0],     ahi[mt][1], alo[mt][1]);
                split_tf32(wp[4],          ahi[mt][2], alo[mt][2]);
                split_tf32(wp[8 * C0 + 4], ahi[mt][3], alo[mt][3]);
            }
            uint32_t bhi[NT][2], blo[NT][2];
#pragma unroll
            for (int n = 0; n < NT; n++) {
                const float* xp = mid + (ks * 8 + tl) * LDX + n * 8 + gid;
                split_tf32(xp[0],       bhi[n][0], blo[n][0]);
                split_tf32(xp[4 * LDX], bhi[n][1], blo[n][1]);
            }
#pragma unroll
            for (int mt = 0; mt < MT1; mt++)
#pragma unroll
                for (int n = 0; n < NT; n++) {
                    mma_tf32(acc[mt][n], ahi[mt], blo[n]);
                    mma_tf32(acc[mt][n], alo[mt], bhi[n]);
                    mma_tf32(acc[mt][n], ahi[mt], bhi[n]);
                }
        }
        // maxpool over NS columns + relu + store
#pragma unroll
        for (int mt = 0; mt < MT1; mt++) {
            float m0 = -3.4e38f, m1 = -3.4e38f;
#pragma unroll
            for (int n = 0; n < NT; n++) {
                m0 = fmaxf(m0, fmaxf(acc[mt][n][0], acc[mt][n][1]));
                m1 = fmaxf(m1, fmaxf(acc[mt][n][2], acc[mt][n][3]));
            }
            m0 = fmaxf(m0, __shfl_xor_sync(0xffffffffu, m0, 1));
            m0 = fmaxf(m0, __shfl_xor_sync(0xffffffffu, m0, 2));
            m1 = fmaxf(m1, __shfl_xor_sync(0xffffffffu, m1, 1));
            m1 = fmaxf(m1, __shfl_xor_sync(0xffffffffu, m1, 2));
            if (tl == 0) {
                int r0 = warp * MT1 * 16 + mt * 16 + gid;
                float v0 = fmaxf(m0, 0.0f);
                float v1 = fmaxf(m1, 0.0f);
                if (FINAL) {
                    out[(size_t)b * C1 * S + (size_t)r0 * S + s] = v0;
                    out[(size_t)b * C1 * S + (size_t)(r0 + 8) * S + s] = v1;
                } else {
                    out[(size_t)gs * C1 + r0] = v0;
                    out[(size_t)gs * C1 + r0 + 8] = v1;
                }
            }
        }
    }
}

// ---------------------------------------------------------------------------
extern "C" void kernel_launch(void* const* d_in, const int* in_sizes, int n_in,
                              void* d_out, int out_size)
{
    (void)in_sizes; (void)n_in; (void)out_size;
    const float* pc = (const float*)d_in[0];

    float *nx1, *nx2, *nx3, *f1, *f2;
    int* idxb;
    float *w0T, *w1T, *w2M, *w3M, *w4M, *w5M;
    float *b0, *b1, *b2, *b3, *b4, *b5;
    cudaGetSymbolAddress((void**)&nx1, g_nx1);
    cudaGetSymbolAddress((void**)&nx2, g_nx2);
    cudaGetSymbolAddress((void**)&nx3, g_nx3);
    cudaGetSymbolAddress((void**)&idxb, g_idxbuf);
    cudaGetSymbolAddress((void**)&f1, g_f1);
    cudaGetSymbolAddress((void**)&f2, g_f2);
    cudaGetSymbolAddress((void**)&w0T, g_w0T); cudaGetSymbolAddress((void**)&b0, g_b0);
    cudaGetSymbolAddress((void**)&w1T, g_w1T); cudaGetSymbolAddress((void**)&b1, g_b1);
    cudaGetSymbolAddress((void**)&w2M, g_w2M); cudaGetSymbolAddress((void**)&b2, g_b2);
    cudaGetSymbolAddress((void**)&w3M, g_w3M); cudaGetSymbolAddress((void**)&b3, g_b3);
    cudaGetSymbolAddress((void**)&w4M, g_w4M); cudaGetSymbolAddress((void**)&b4, g_b4);
    cudaGetSymbolAddress((void**)&w5M, g_w5M); cudaGetSymbolAddress((void**)&b5, g_b5);

    FoldArgs fa;
    const int cins[6]  = {9, 32, 67, 128, 131, 256};
    const int cinPs[6] = {6, 32, 72, 128, 136, 256};   // l0: folded-6 (k-major)
    const int couts[6] = {32, 64, 128, 128, 256, 256};
    float* wTs[6] = {w0T, w1T, w2M, w3M, w4M, w5M};
    float* bss[6] = {b0, b1, b2, b3, b4, b5};
    for (int l = 0; l < 6; l++) {
        fa.w[l]  = (const float*)d_in[1 + 5 * l];
        fa.g[l]  = (const float*)d_in[2 + 5 * l];
        fa.be[l] = (const float*)d_in[3 + 5 * l];
        fa.rm[l] = (const float*)d_in[4 + 5 * l];
        fa.rv[l] = (const float*)d_in[5 + 5 * l];
        fa.wT[l] = wTs[l]; fa.bias[l] = bss[l];
        fa.cin[l] = cins[l]; fa.cinP[l] = cinPs[l]; fa.cout[l] = couts[l];
    }
    fold_all_kernel<<<dim3(72, 6), 256>>>(fa);

    const float rr0 = (float)(0.02 * 0.02);
    const float rr1 = (float)(0.04 * 0.04);
    const float rr2 = (float)(0.08 * 0.08);

    // smem bytes
    const int smem0 = ((6 + 32) * 132 + 512) * 4;            // 22112 (stage0 SIMT)
    const int smem1 = (72 + 128) * 40 * 4;                   // 32000 (stage1 mma)
    const int smem2 = (136 + 256) * 24 * 4;                  // 37632 (stage2 mma)

    auto k0 = sa_mlp0_kernel<6, 32, 64, 32, 4, 128, 8, 16>;
    // stage1: C0=128,C1=128,K0=67->72,NS=32,LDX=40
    auto k1 = sa_mma_kernel<128, 128, 67, 72, 32, 40, false>;
    // stage2: C0=256,C1=256,K0=131->136,NS=16,LDX=24
    auto k2 = sa_mma_kernel<256, 256, 131, 136, 16, 24, true>;

    // ---- stage 0: N=4096 -> S=128 ----
    fps_kernel<4096, 128, 256><<<B, 256>>>(pc, nx1);
    ballquery_kernel<32><<<(B * S0) / 4, 128>>>(nx1, pc, idxb, N0, S0, rr0);
    k0<<<(B * S0) / 4, 128, smem0>>>(pc, nx1, idxb, w0T, b0, w1T, b1, f1, N0, S0);

    // ---- stage 1: N=128 -> S=64 ----
    fps_kernel<128, 64, 128><<<B, 128>>>(nx1, nx2);
    ballquery_kernel<32><<<(B * S1) / 4, 128>>>(nx2, nx1, idxb, S0, S1, rr1);
    k1<<<B * S1, 128, smem1>>>(nx1, f1, nx2, idxb, w2M, b2, w3M, b3, f2, S0, S1);

    // ---- stage 2: N=64 -> S=32 ----
    fps_kernel<64, 32, 64><<<B, 64>>>(nx2, nx3);
    ballquery_kernel<16><<<(B * S2) / 4, 128>>>(nx3, nx2, idxb, S1, S2, rr2);
    k2<<<B * S2, 128, smem2>>>(nx2, f2, nx3, idxb, w4M, b4, w5M, b5, (float*)d_out, S1, S2);
}